// round 5
// baseline (speedup 1.0000x reference)
#include <cuda_runtime.h>
#include <cuda_bf16.h>
#include <cstdint>

typedef unsigned long long ull;

#define NPTS  10000
#define NPAD  10016
#define DDIM  3072

// ---------------- device scratch ----------------
__device__ __align__(16) float g_cp[4 * 16 * NPAD];   // cross partials [kq][b][n]
__device__ __align__(16) float g_ip[4 * NPAD];        // ||img||^2 partials [kq][n]
__device__ __align__(16) float g_lg[16 * NPAD];       // logits [b][n]
__device__ __align__(16) float g_w [NPAD * 16];       // unnormalized weights [n][b]
__device__ __align__(16) float g_mp[4 * 16 * DDIM];   // mix partials [quarter][b][d]
__device__ __align__(16) float g_xt[DDIM * 16];       // x transposed [k][b]
__device__ float g_pmax[16 * 8];                      // partial max [b][seg]
__device__ float g_psum[16 * 128];                    // partial sums [b][cta]
__device__ float g_c[4];                              // at, bt2, c1, c2

// ---------------- packed f32x2 helpers ----------------
__device__ __forceinline__ ull dup2(float v) {
    ull r; asm("mov.b64 %0, {%1, %1};" : "=l"(r) : "f"(v)); return r;
}
__device__ __forceinline__ void fma2(ull& d, ull a, ull b) {
    asm("fma.rn.f32x2 %0, %1, %2, %0;" : "+l"(d) : "l"(a), "l"(b));
}
__device__ __forceinline__ void unpack2(ull v, float& lo, float& hi) {
    asm("mov.b64 {%0, %1}, %2;" : "=f"(lo), "=f"(hi) : "l"(v));
}

// ---------------- L0: constants (launch 0) ----------------
__global__ void kconst(const float* __restrict__ sval) {
    if (threadIdx.x == 0) {
        float s = sval[0];
        float at = sqrtf(1.f - s);
        g_c[0] = at;
        g_c[1] = s;                        // bt2
        g_c[2] = at / s;                   // c1
        g_c[3] = -(at * at) / (2.f * s);   // c2
    }
}

// ---------------- L1/L2: transpose x (launches 1,2) ----------------
__global__ __launch_bounds__(256) void ktr(const float* __restrict__ x, int off) {
    int i = off + blockIdx.x * 256 + threadIdx.x;   // i = k*16 + b
    if (i < DDIM * 16) {
        int b = i & 15, k = i >> 4;
        g_xt[i] = x[b * DDIM + k];
    }
}

// ---------------- L3: k1  cross + isq (628 CTAs x 256) ----------------
// CTA c: n-tile = c>>2 (64 rows), k-quarter kq = c&3 (768 k). 24 chunks of 32 k.
// Thread (n_l = t&63, kp = t>>6): 8 k per chunk, all 16 b as 8 f32x2 accs.
__global__ __launch_bounds__(256) void k1(const float* __restrict__ img) {
    __shared__ float sbuf[2][64 * 32];   // 2 x 8KB, XOR-swizzled rows of 128B
    __shared__ float xts[2][32 * 16];    // 2 x 2KB
    __shared__ float2 red[256];

    const int t = threadIdx.x, c = blockIdx.x;
    const int tile = c >> 2, kq = c & 3;
    const int n0 = tile * 64, k0 = kq * 768;
    const int n_l = t & 63, kp = t >> 6;
    const int lrow = t >> 3, lc4 = t & 7;
    const int rA = n0 + lrow, rB = n0 + lrow + 32;
    const int swA = lrow * 32 + ((lc4 ^ (lrow & 7)) << 2);
    const int swB = (lrow + 32) * 32 + ((lc4 ^ (lrow & 7)) << 2);
    const float4 z4 = make_float4(0.f, 0.f, 0.f, 0.f);

    ull acc[8];
#pragma unroll
    for (int j = 0; j < 8; j++) acc[j] = 0ULL;
    float isq = 0.f;

    float4 pA, pB, pX = z4;
    // prefetch + stage chunk 0
    {
        int kk0 = k0;
        pA = (rA < NPTS) ? *(const float4*)(img + (size_t)rA * DDIM + kk0 + lc4 * 4) : z4;
        pB = (rB < NPTS) ? *(const float4*)(img + (size_t)rB * DDIM + kk0 + lc4 * 4) : z4;
        if (t < 128) pX = ((const float4*)(g_xt + (size_t)kk0 * 16))[t];
        *(float4*)&sbuf[0][swA] = pA;
        *(float4*)&sbuf[0][swB] = pB;
        if (t < 128) ((float4*)xts[0])[t] = pX;
    }
    __syncthreads();

    const int p0 = n_l * 32 + (((2 * kp) ^ (n_l & 7)) << 2);
    const int p1 = n_l * 32 + (((2 * kp + 1) ^ (n_l & 7)) << 2);
    const int xo = kp * 8 * 16;

    for (int ch = 0; ch < 24; ch++) {
        const int s = ch & 1;
        if (ch + 1 < 24) {   // prefetch next chunk (overlaps compute)
            int kk0 = k0 + (ch + 1) * 32;
            pA = (rA < NPTS) ? *(const float4*)(img + (size_t)rA * DDIM + kk0 + lc4 * 4) : z4;
            pB = (rB < NPTS) ? *(const float4*)(img + (size_t)rB * DDIM + kk0 + lc4 * 4) : z4;
            if (t < 128) pX = ((const float4*)(g_xt + (size_t)kk0 * 16))[t];
        }
        // compute on buffer s
        const float* sb = sbuf[s];
        const float* xt = xts[s];
        float4 v0 = *(const float4*)&sb[p0];
        float4 v1 = *(const float4*)&sb[p1];
        float fv[8] = { v0.x, v0.y, v0.z, v0.w, v1.x, v1.y, v1.z, v1.w };
#pragma unroll
        for (int kk = 0; kk < 8; kk++) {
            float f = fv[kk];
            isq = fmaf(f, f, isq);
            ull dv = dup2(f);
            const ulonglong2* xr = (const ulonglong2*)(xt + xo + kk * 16);
#pragma unroll
            for (int j = 0; j < 4; j++) {
                ulonglong2 u = xr[j];
                fma2(acc[2 * j],     u.x, dv);
                fma2(acc[2 * j + 1], u.y, dv);
            }
        }
        __syncthreads();
        if (ch + 1 < 24) {
            *(float4*)&sbuf[s ^ 1][swA] = pA;
            *(float4*)&sbuf[s ^ 1][swB] = pB;
            if (t < 128) ((float4*)xts[s ^ 1])[t] = pX;
            __syncthreads();
        }
    }

    // epilogue: reduce over kp (threads n_l, n_l+64, n_l+128, n_l+192)
#pragma unroll 1
    for (int bp = 0; bp < 8; bp++) {
        __syncthreads();
        float lo, hi; unpack2(acc[bp], lo, hi);
        red[t] = make_float2(lo, hi);
        __syncthreads();
        if (t < 64) {
            float2 s0 = red[t], s1 = red[t + 64], s2 = red[t + 128], s3 = red[t + 192];
            float sx = s0.x + s1.x + s2.x + s3.x;
            float sy = s0.y + s1.y + s2.y + s3.y;
            int n = n0 + t;
            if (n < NPTS) {
                g_cp[(kq * 16 + 2 * bp) * NPAD + n] = sx;
                g_cp[(kq * 16 + 2 * bp + 1) * NPAD + n] = sy;
            }
        }
    }
    __syncthreads();
    ((float*)red)[t] = isq;
    __syncthreads();
    if (t < 64) {
        const float* r = (const float*)red;
        float s = r[t] + r[t + 64] + r[t + 128] + r[t + 192];
        int n = n0 + t;
        if (n < NPTS) g_ip[kq * NPAD + n] = s;
    }
}

// ---------------- L4: s1  logits + partial max (128 CTAs) ----------------
__global__ __launch_bounds__(256) void s1() {
    const int t = threadIdx.x, c = blockIdx.x;
    const int b = c >> 3, seg = c & 7;
    const float c1 = g_c[2], c2 = g_c[3];
    const int nbase = seg * 1252;
    const int nend = min(nbase + 1252, NPTS);
    float m = -1e30f;
    for (int i = nbase + t; i < nend; i += 256) {
        float cr = g_cp[b * NPAD + i] + g_cp[(16 + b) * NPAD + i]
                 + g_cp[(32 + b) * NPAD + i] + g_cp[(48 + b) * NPAD + i];
        float qq = g_ip[i] + g_ip[NPAD + i] + g_ip[2 * NPAD + i] + g_ip[3 * NPAD + i];
        float lg = fmaf(c1, cr, c2 * qq);
        g_lg[b * NPAD + i] = lg;
        m = fmaxf(m, lg);
    }
    __shared__ float wm[8];
    for (int o = 16; o; o >>= 1) m = fmaxf(m, __shfl_xor_sync(0xffffffffu, m, o));
    if ((t & 31) == 0) wm[t >> 5] = m;
    __syncthreads();
    if (t == 0) {
        float v = wm[0];
        for (int w = 1; w < 8; w++) v = fmaxf(v, wm[w]);
        g_pmax[c] = v;
    }
}

// ---------------- L5: s3  exp + unnormalized w + partial sums (128 CTAs) ----------------
__global__ __launch_bounds__(256) void s3() {
    const int t = threadIdx.x, c = blockIdx.x;
    const int bb = t & 15, nn = t >> 4;
    const float L2E = 1.44269504088896340736f;
    float M = g_pmax[bb * 8];
#pragma unroll
    for (int s = 1; s < 8; s++) M = fmaxf(M, g_pmax[bb * 8 + s]);
    const int base = c * 79;
    float sum = 0.f;
#pragma unroll
    for (int r = 0; r < 5; r++) {
        int n = base + nn + 16 * r;
        if (n < base + 79 && n < NPTS) {
            float e = exp2f((g_lg[bb * NPAD + n] - M) * L2E);
            g_w[n * 16 + bb] = e;
            sum += e;
        }
    }
    sum += __shfl_xor_sync(0xffffffffu, sum, 16);
    __shared__ float sm[8 * 16];
    if ((t & 31) < 16) sm[(t >> 5) * 16 + bb] = sum;
    __syncthreads();
    if (t < 16) {
        float s = 0.f;
        for (int w = 0; w < 8; w++) s += sm[w * 16 + t];
        g_psum[t * 128 + c] = s;
    }
}

// ---------------- L6: k3  mix partials (384 CTAs x 256) ----------------
// CTA c: d-tile = c>>2 (32 cols), quarter = c&3 (2500 n). Thread: dt=t&7 (4 cols),
// bh=(t>>3)&1 (8 b), p=t>>4 (16-way n partition). acc[bp][d] f32x2.
__global__ __launch_bounds__(256) void k3(const float* __restrict__ img) {
    __shared__ float red[256 * 8];
    const int t = threadIdx.x, c = blockIdx.x;
    const int dtile = c >> 2, quarter = c & 3;
    const int dt = t & 7, bh = (t >> 3) & 1, p = t >> 4;
    const int dbase = dtile * 32 + dt * 4;
    const int q0 = quarter * 2500;

    ull acc[4][4];
#pragma unroll
    for (int i = 0; i < 4; i++)
#pragma unroll
        for (int j = 0; j < 4; j++) acc[i][j] = 0ULL;

#pragma unroll 1
    for (int j = 0; j < 156; j += 2) {
        int n1 = q0 + p + 16 * j, n2 = n1 + 16;
        float4 i1 = *(const float4*)(img + (size_t)n1 * DDIM + dbase);
        float4 i2 = *(const float4*)(img + (size_t)n2 * DDIM + dbase);
        ulonglong2 wa1 = *(const ulonglong2*)(g_w + (size_t)n1 * 16 + bh * 8);
        ulonglong2 wb1 = *(const ulonglong2*)(g_w + (size_t)n1 * 16 + bh * 8 + 4);
        ulonglong2 wa2 = *(const ulonglong2*)(g_w + (size_t)n2 * 16 + bh * 8);
        ulonglong2 wb2 = *(const ulonglong2*)(g_w + (size_t)n2 * 16 + bh * 8 + 4);
#pragma unroll
        for (int d = 0; d < 4; d++) {
            ull dv = dup2((&i1.x)[d]);
            fma2(acc[0][d], wa1.x, dv);
            fma2(acc[1][d], wa1.y, dv);
            fma2(acc[2][d], wb1.x, dv);
            fma2(acc[3][d], wb1.y, dv);
        }
#pragma unroll
        for (int d = 0; d < 4; d++) {
            ull dv = dup2((&i2.x)[d]);
            fma2(acc[0][d], wa2.x, dv);
            fma2(acc[1][d], wa2.y, dv);
            fma2(acc[2][d], wb2.x, dv);
            fma2(acc[3][d], wb2.y, dv);
        }
    }
    // tail: n = q0+2496..2499 handled by p<4
    if (p < 4) {
        int n = q0 + 2496 + p;
        float4 i1 = *(const float4*)(img + (size_t)n * DDIM + dbase);
        ulonglong2 wa = *(const ulonglong2*)(g_w + (size_t)n * 16 + bh * 8);
        ulonglong2 wb = *(const ulonglong2*)(g_w + (size_t)n * 16 + bh * 8 + 4);
#pragma unroll
        for (int d = 0; d < 4; d++) {
            ull dv = dup2((&i1.x)[d]);
            fma2(acc[0][d], wa.x, dv);
            fma2(acc[1][d], wa.y, dv);
            fma2(acc[2][d], wb.x, dv);
            fma2(acc[3][d], wb.y, dv);
        }
    }

    // reduce over p (16) per (b, col)
#pragma unroll 1
    for (int bp = 0; bp < 4; bp++) {
        __syncthreads();
#pragma unroll
        for (int d = 0; d < 4; d++) {
            float lo, hi; unpack2(acc[bp][d], lo, hi);
            red[t * 8 + 2 * d] = lo;
            red[t * 8 + 2 * d + 1] = hi;
        }
        __syncthreads();
        if (t < 128) {
            int h = t & 1, d = (t >> 1) & 3, dtw = (t >> 3) & 7, bhw = t >> 6;
            float s = 0.f;
#pragma unroll
            for (int p2 = 0; p2 < 16; p2++)
                s += red[(dtw + bhw * 8 + p2 * 16) * 8 + 2 * d + h];
            int b = bhw * 8 + bp * 2 + h;
            g_mp[(quarter * 16 + b) * DDIM + dtile * 32 + dtw * 4 + d] = s;
        }
    }
}

// ---------------- L7: k4  combine + normalize + final (48 CTAs x 256) ----------------
__global__ __launch_bounds__(256) void k4(const float* __restrict__ x,
                                          float* __restrict__ out) {
    const int t = threadIdx.x, c = blockIdx.x;
    const int blo = (c * 1024) / DDIM;
    const int bhi = ((c + 1) * 1024 - 1) / DDIM;
    __shared__ float wsum[8];
    __shared__ float invs[2];
    {
        int myb = (t < 128) ? blo : bhi;
        float s = g_psum[myb * 128 + (t & 127)];
        for (int o = 16; o; o >>= 1) s += __shfl_xor_sync(0xffffffffu, s, o);
        if ((t & 31) == 0) wsum[t >> 5] = s;
    }
    __syncthreads();
    if (t == 0)   invs[0] = 1.f / (wsum[0] + wsum[1] + wsum[2] + wsum[3]);
    if (t == 128) invs[1] = 1.f / (wsum[4] + wsum[5] + wsum[6] + wsum[7]);
    __syncthreads();

    const float at = g_c[0], bt2 = g_c[1];
    int i = (c * 256 + t) * 4;
    int b = i / DDIM;
    int d = i - b * DDIM;
    float inv = (b == blo) ? invs[0] : invs[1];
    float4 m0 = *(const float4*)(g_mp + (size_t)b * DDIM + d);
    float4 m1 = *(const float4*)(g_mp + (size_t)(16 + b) * DDIM + d);
    float4 m2 = *(const float4*)(g_mp + (size_t)(32 + b) * DDIM + d);
    float4 m3 = *(const float4*)(g_mp + (size_t)(48 + b) * DDIM + d);
    float4 xv = *(const float4*)(x + i);
    float sc = at * inv / bt2;
    float4 o;
    o.x = sc * (m0.x + m1.x + m2.x + m3.x) - xv.x / bt2;
    o.y = sc * (m0.y + m1.y + m2.y + m3.y) - xv.y / bt2;
    o.z = sc * (m0.z + m1.z + m2.z + m3.z) - xv.z / bt2;
    o.w = sc * (m0.w + m1.w + m2.w + m3.w) - xv.w / bt2;
    *(float4*)(out + i) = o;
}

// ---------------- launch ----------------
extern "C" void kernel_launch(void* const* d_in, const int* in_sizes, int n_in,
                              void* d_out, int out_size) {
    const float* x    = (const float*)d_in[0];
    const float* img  = (const float*)d_in[1];
    const float* sval = (const float*)d_in[2];
    float* out = (float*)d_out;

    kconst<<<1, 32>>>(sval);                 // 0
    ktr<<<96, 256>>>(x, 0);                  // 1  (k < 1536)
    ktr<<<96, 256>>>(x, 24576);              // 2  (k >= 1536)
    k1<<<628, 256>>>(img);                   // 3  <- ncu capture lands here
    s1<<<128, 256>>>();                      // 4
    s3<<<128, 256>>>();                      // 5
    k3<<<384, 256>>>(img);                   // 6
    k4<<<48, 256>>>(x, out);                 // 7
}

// round 7
// speedup vs baseline: 1.0201x; 1.0201x over previous
#include <cuda_runtime.h>
#include <cuda_bf16.h>
#include <cstdint>

typedef unsigned long long ull;

#define NPTS  10000
#define NPAD  10016
#define DDIM  3072

// ---------------- device scratch ----------------
__device__ __align__(16) float g_cp[4 * 16 * NPAD];   // cross partials [kq][b][n]
__device__ __align__(16) float g_ip[4 * NPAD];        // ||img||^2 partials [kq][n]
__device__ __align__(16) float g_lg[16 * NPAD];       // logits [b][n]
__device__ __align__(16) float g_w [NPAD * 16];       // unnormalized weights [n][b]
__device__ __align__(16) float g_mp[4 * 16 * DDIM];   // mix partials [quarter][b][d]
__device__ __align__(16) float g_xt[DDIM * 16];       // x transposed [k][b]
__device__ float g_pmax[16 * 8];                      // partial max [b][seg]
__device__ float g_psum[16 * 128];                    // partial sums [b][cta]
__device__ float g_c[4];                              // at, bt2, c1, c2

// ---------------- packed f32x2 helpers ----------------
__device__ __forceinline__ ull dup2(float v) {
    ull r; asm("mov.b64 %0, {%1, %1};" : "=l"(r) : "f"(v)); return r;
}
__device__ __forceinline__ void fma2(ull& d, ull a, ull b) {
    asm("fma.rn.f32x2 %0, %1, %2, %0;" : "+l"(d) : "l"(a), "l"(b));
}
__device__ __forceinline__ void unpack2(ull v, float& lo, float& hi) {
    asm("mov.b64 {%0, %1}, %2;" : "=f"(lo), "=f"(hi) : "l"(v));
}

// ---------------- L0: constants (launch 0) ----------------
__global__ void kconst(const float* __restrict__ sval) {
    if (threadIdx.x == 0) {
        float s = sval[0];
        float at = sqrtf(1.f - s);
        g_c[0] = at;
        g_c[1] = s;                        // bt2
        g_c[2] = at / s;                   // c1
        g_c[3] = -(at * at) / (2.f * s);   // c2
    }
}

// ---------------- L1/L2: transpose x (launches 1,2) ----------------
__global__ __launch_bounds__(256) void ktr(const float* __restrict__ x, int off) {
    int i = off + blockIdx.x * 256 + threadIdx.x;   // i = k*16 + b
    if (i < DDIM * 16) {
        int b = i & 15, k = i >> 4;
        g_xt[i] = x[b * DDIM + k];
    }
}

// ---------------- L3: k1  cross + isq (628 CTAs x 256) ----------------
// CTA c: n-tile = c>>2 (64 rows), k-quarter kq = c&3 (768 k). 24 chunks of 32 k.
// Thread (n_l = t&63, kp = t>>6): 8 k per chunk, all 16 b as 8 f32x2 accs.
__global__ __launch_bounds__(256) void k1(const float* __restrict__ img) {
    __shared__ float sbuf[2][64 * 32];   // 2 x 8KB, XOR-swizzled rows of 128B
    __shared__ float xts[2][32 * 16];    // 2 x 2KB
    __shared__ float2 red[256];

    const int t = threadIdx.x, c = blockIdx.x;
    const int tile = c >> 2, kq = c & 3;
    const int n0 = tile * 64, k0 = kq * 768;
    const int n_l = t & 63, kp = t >> 6;
    const int lrow = t >> 3, lc4 = t & 7;
    const int rA = n0 + lrow, rB = n0 + lrow + 32;
    const int swA = lrow * 32 + ((lc4 ^ (lrow & 7)) << 2);
    const int swB = (lrow + 32) * 32 + ((lc4 ^ (lrow & 7)) << 2);
    const float4 z4 = make_float4(0.f, 0.f, 0.f, 0.f);

    ull acc[8];
#pragma unroll
    for (int j = 0; j < 8; j++) acc[j] = 0ULL;
    float isq = 0.f;

    float4 pA, pB, pX = z4;
    // prefetch + stage chunk 0
    {
        int kk0 = k0;
        pA = (rA < NPTS) ? *(const float4*)(img + (size_t)rA * DDIM + kk0 + lc4 * 4) : z4;
        pB = (rB < NPTS) ? *(const float4*)(img + (size_t)rB * DDIM + kk0 + lc4 * 4) : z4;
        if (t < 128) pX = ((const float4*)(g_xt + (size_t)kk0 * 16))[t];
        *(float4*)&sbuf[0][swA] = pA;
        *(float4*)&sbuf[0][swB] = pB;
        if (t < 128) ((float4*)xts[0])[t] = pX;
    }
    __syncthreads();

    const int p0 = n_l * 32 + (((2 * kp) ^ (n_l & 7)) << 2);
    const int p1 = n_l * 32 + (((2 * kp + 1) ^ (n_l & 7)) << 2);
    const int xo = kp * 8 * 16;

    for (int ch = 0; ch < 24; ch++) {
        const int s = ch & 1;
        if (ch + 1 < 24) {   // prefetch next chunk (overlaps compute)
            int kk0 = k0 + (ch + 1) * 32;
            pA = (rA < NPTS) ? *(const float4*)(img + (size_t)rA * DDIM + kk0 + lc4 * 4) : z4;
            pB = (rB < NPTS) ? *(const float4*)(img + (size_t)rB * DDIM + kk0 + lc4 * 4) : z4;
            if (t < 128) pX = ((const float4*)(g_xt + (size_t)kk0 * 16))[t];
        }
        // compute on buffer s
        const float* sb = sbuf[s];
        const float* xt = xts[s];
        float4 v0 = *(const float4*)&sb[p0];
        float4 v1 = *(const float4*)&sb[p1];
        float fv[8] = { v0.x, v0.y, v0.z, v0.w, v1.x, v1.y, v1.z, v1.w };
#pragma unroll
        for (int kk = 0; kk < 8; kk++) {
            float f = fv[kk];
            isq = fmaf(f, f, isq);
            ull dv = dup2(f);
            const ulonglong2* xr = (const ulonglong2*)(xt + xo + kk * 16);
#pragma unroll
            for (int j = 0; j < 4; j++) {
                ulonglong2 u = xr[j];
                fma2(acc[2 * j],     u.x, dv);
                fma2(acc[2 * j + 1], u.y, dv);
            }
        }
        __syncthreads();
        if (ch + 1 < 24) {
            *(float4*)&sbuf[s ^ 1][swA] = pA;
            *(float4*)&sbuf[s ^ 1][swB] = pB;
            if (t < 128) ((float4*)xts[s ^ 1])[t] = pX;
            __syncthreads();
        }
    }

    // epilogue: reduce over kp (threads n_l, n_l+64, n_l+128, n_l+192)
#pragma unroll 1
    for (int bp = 0; bp < 8; bp++) {
        __syncthreads();
        float lo, hi; unpack2(acc[bp], lo, hi);
        red[t] = make_float2(lo, hi);
        __syncthreads();
        if (t < 64) {
            float2 s0 = red[t], s1 = red[t + 64], s2 = red[t + 128], s3 = red[t + 192];
            float sx = s0.x + s1.x + s2.x + s3.x;
            float sy = s0.y + s1.y + s2.y + s3.y;
            int n = n0 + t;
            if (n < NPTS) {
                g_cp[(kq * 16 + 2 * bp) * NPAD + n] = sx;
                g_cp[(kq * 16 + 2 * bp + 1) * NPAD + n] = sy;
            }
        }
    }
    __syncthreads();
    ((float*)red)[t] = isq;
    __syncthreads();
    if (t < 64) {
        const float* r = (const float*)red;
        float s = r[t] + r[t + 64] + r[t + 128] + r[t + 192];
        int n = n0 + t;
        if (n < NPTS) g_ip[kq * NPAD + n] = s;
    }
}

// ---------------- L4: s1  logits + partial max (128 CTAs) ----------------
__global__ __launch_bounds__(256) void s1() {
    const int t = threadIdx.x, c = blockIdx.x;
    const int b = c >> 3, seg = c & 7;
    const float c1 = g_c[2], c2 = g_c[3];
    const int nbase = seg * 1252;
    const int nend = min(nbase + 1252, NPTS);
    float m = -1e30f;
    for (int i = nbase + t; i < nend; i += 256) {
        float cr = g_cp[b * NPAD + i] + g_cp[(16 + b) * NPAD + i]
                 + g_cp[(32 + b) * NPAD + i] + g_cp[(48 + b) * NPAD + i];
        float qq = g_ip[i] + g_ip[NPAD + i] + g_ip[2 * NPAD + i] + g_ip[3 * NPAD + i];
        float lg = fmaf(c1, cr, c2 * qq);
        g_lg[b * NPAD + i] = lg;
        m = fmaxf(m, lg);
    }
    __shared__ float wm[8];
    for (int o = 16; o; o >>= 1) m = fmaxf(m, __shfl_xor_sync(0xffffffffu, m, o));
    if ((t & 31) == 0) wm[t >> 5] = m;
    __syncthreads();
    if (t == 0) {
        float v = wm[0];
        for (int w = 1; w < 8; w++) v = fmaxf(v, wm[w]);
        g_pmax[c] = v;
    }
}

// ---------------- L5: s3  exp + unnormalized w + partial sums (128 CTAs) ----------------
__global__ __launch_bounds__(256) void s3() {
    const int t = threadIdx.x, c = blockIdx.x;
    const int bb = t & 15, nn = t >> 4;
    const float L2E = 1.44269504088896340736f;
    float M = g_pmax[bb * 8];
#pragma unroll
    for (int s = 1; s < 8; s++) M = fmaxf(M, g_pmax[bb * 8 + s]);
    const int base = c * 79;
    float sum = 0.f;
#pragma unroll
    for (int r = 0; r < 5; r++) {
        int n = base + nn + 16 * r;
        if (n < base + 79 && n < NPTS) {
            float e = exp2f((g_lg[bb * NPAD + n] - M) * L2E);
            g_w[n * 16 + bb] = e;
            sum += e;
        }
    }
    sum += __shfl_xor_sync(0xffffffffu, sum, 16);
    __shared__ float sm[8 * 16];
    if ((t & 31) < 16) sm[(t >> 5) * 16 + bb] = sum;
    __syncthreads();
    if (t < 16) {
        float s = 0.f;
        for (int w = 0; w < 8; w++) s += sm[w * 16 + t];
        g_psum[t * 128 + c] = s;
    }
}

// ---------------- L6: k3  mix partials (384 CTAs x 256) ----------------
// CTA c: d-tile = c>>2 (32 cols), quarter = c&3 (2500 n). Thread: dt=t&7 (4 cols),
// bh=(t>>3)&1 (8 b), p=t>>4 (16-way n partition). acc[bp][d] f32x2.
__global__ __launch_bounds__(256) void k3(const float* __restrict__ img) {
    __shared__ float red[256 * 8];
    const int t = threadIdx.x, c = blockIdx.x;
    const int dtile = c >> 2, quarter = c & 3;
    const int dt = t & 7, bh = (t >> 3) & 1, p = t >> 4;
    const int dbase = dtile * 32 + dt * 4;
    const int q0 = quarter * 2500;

    ull acc[4][4];
#pragma unroll
    for (int i = 0; i < 4; i++)
#pragma unroll
        for (int j = 0; j < 4; j++) acc[i][j] = 0ULL;

#pragma unroll 1
    for (int j = 0; j < 156; j += 2) {
        int n1 = q0 + p + 16 * j, n2 = n1 + 16;
        float4 i1 = *(const float4*)(img + (size_t)n1 * DDIM + dbase);
        float4 i2 = *(const float4*)(img + (size_t)n2 * DDIM + dbase);
        ulonglong2 wa1 = *(const ulonglong2*)(g_w + (size_t)n1 * 16 + bh * 8);
        ulonglong2 wb1 = *(const ulonglong2*)(g_w + (size_t)n1 * 16 + bh * 8 + 4);
        ulonglong2 wa2 = *(const ulonglong2*)(g_w + (size_t)n2 * 16 + bh * 8);
        ulonglong2 wb2 = *(const ulonglong2*)(g_w + (size_t)n2 * 16 + bh * 8 + 4);
#pragma unroll
        for (int d = 0; d < 4; d++) {
            ull dv = dup2((&i1.x)[d]);
            fma2(acc[0][d], wa1.x, dv);
            fma2(acc[1][d], wa1.y, dv);
            fma2(acc[2][d], wb1.x, dv);
            fma2(acc[3][d], wb1.y, dv);
        }
#pragma unroll
        for (int d = 0; d < 4; d++) {
            ull dv = dup2((&i2.x)[d]);
            fma2(acc[0][d], wa2.x, dv);
            fma2(acc[1][d], wa2.y, dv);
            fma2(acc[2][d], wb2.x, dv);
            fma2(acc[3][d], wb2.y, dv);
        }
    }
    // tail: n = q0+2496..2499 handled by p<4
    if (p < 4) {
        int n = q0 + 2496 + p;
        float4 i1 = *(const float4*)(img + (size_t)n * DDIM + dbase);
        ulonglong2 wa = *(const ulonglong2*)(g_w + (size_t)n * 16 + bh * 8);
        ulonglong2 wb = *(const ulonglong2*)(g_w + (size_t)n * 16 + bh * 8 + 4);
#pragma unroll
        for (int d = 0; d < 4; d++) {
            ull dv = dup2((&i1.x)[d]);
            fma2(acc[0][d], wa.x, dv);
            fma2(acc[1][d], wa.y, dv);
            fma2(acc[2][d], wb.x, dv);
            fma2(acc[3][d], wb.y, dv);
        }
    }

    // reduce over p (16) per (b, col)
#pragma unroll 1
    for (int bp = 0; bp < 4; bp++) {
        __syncthreads();
#pragma unroll
        for (int d = 0; d < 4; d++) {
            float lo, hi; unpack2(acc[bp][d], lo, hi);
            red[t * 8 + 2 * d] = lo;
            red[t * 8 + 2 * d + 1] = hi;
        }
        __syncthreads();
        if (t < 128) {
            int h = t & 1, d = (t >> 1) & 3, dtw = (t >> 3) & 7, bhw = t >> 6;
            float s = 0.f;
#pragma unroll
            for (int p2 = 0; p2 < 16; p2++)
                s += red[(dtw + bhw * 8 + p2 * 16) * 8 + 2 * d + h];
            int b = bhw * 8 + bp * 2 + h;
            g_mp[(quarter * 16 + b) * DDIM + dtile * 32 + dtw * 4 + d] = s;
        }
    }
}

// ---------------- L7: k4  combine + normalize + final (48 CTAs x 256) ----------------
__global__ __launch_bounds__(256) void k4(const float* __restrict__ x,
                                          float* __restrict__ out) {
    const int t = threadIdx.x, c = blockIdx.x;
    const int blo = (c * 1024) / DDIM;
    const int bhi = ((c + 1) * 1024 - 1) / DDIM;
    __shared__ float wsum[8];
    __shared__ float invs[2];
    {
        int myb = (t < 128) ? blo : bhi;
        float s = g_psum[myb * 128 + (t & 127)];
        for (int o = 16; o; o >>= 1) s += __shfl_xor_sync(0xffffffffu, s, o);
        if ((t & 31) == 0) wsum[t >> 5] = s;
    }
    __syncthreads();
    if (t == 0)   invs[0] = 1.f / (wsum[0] + wsum[1] + wsum[2] + wsum[3]);
    if (t == 128) invs[1] = 1.f / (wsum[4] + wsum[5] + wsum[6] + wsum[7]);
    __syncthreads();

    const float at = g_c[0], bt2 = g_c[1];
    int i = (c * 256 + t) * 4;
    int b = i / DDIM;
    int d = i - b * DDIM;
    float inv = (b == blo) ? invs[0] : invs[1];
    float4 m0 = *(const float4*)(g_mp + (size_t)b * DDIM + d);
    float4 m1 = *(const float4*)(g_mp + (size_t)(16 + b) * DDIM + d);
    float4 m2 = *(const float4*)(g_mp + (size_t)(32 + b) * DDIM + d);
    float4 m3 = *(const float4*)(g_mp + (size_t)(48 + b) * DDIM + d);
    float4 xv = *(const float4*)(x + i);
    float sc = at * inv / bt2;
    float4 o;
    o.x = sc * (m0.x + m1.x + m2.x + m3.x) - xv.x / bt2;
    o.y = sc * (m0.y + m1.y + m2.y + m3.y) - xv.y / bt2;
    o.z = sc * (m0.z + m1.z + m2.z + m3.z) - xv.z / bt2;
    o.w = sc * (m0.w + m1.w + m2.w + m3.w) - xv.w / bt2;
    *(float4*)(out + i) = o;
}

// ---------------- launch ----------------
extern "C" void kernel_launch(void* const* d_in, const int* in_sizes, int n_in,
                              void* d_out, int out_size) {
    const float* x    = (const float*)d_in[0];
    const float* img  = (const float*)d_in[1];
    const float* sval = (const float*)d_in[2];
    float* out = (float*)d_out;

    kconst<<<1, 32>>>(sval);                 // 0
    ktr<<<96, 256>>>(x, 0);                  // 1  (k < 1536)
    ktr<<<96, 256>>>(x, 24576);              // 2  (k >= 1536)
    k1<<<628, 256>>>(img);                   // 3  <- ncu capture lands here
    s1<<<128, 256>>>();                      // 4
    s3<<<128, 256>>>();                      // 5
    k3<<<384, 256>>>(img);                   // 6
    k4<<<48, 256>>>(x, out);                 // 7
}